// round 1
// baseline (speedup 1.0000x reference)
#include <cuda_runtime.h>
#include <math.h>

#define BB   8
#define N2   8192
#define N1   2048
#define C1   256
#define C2   128
#define K1   (C1 + C2)        // 384
#define CO   256
#define MTOT (BB * N2)        // 65536

#define STATS_ROWS 64
#define NBLK_STATS (MTOT / STATS_ROWS)   // 1024

// ---------------- scratch (static device globals; no allocations) ----------
__device__ float g_f1t[(size_t)BB * N1 * C1];     // feat1 transposed [b][n1][c1]
__device__ float g_xcat[(size_t)MTOT * K1];       // [b*N2+n][384] = [interp|feat2]
__device__ float g_y1[(size_t)MTOT * CO];         // conv1 pre-BN output [m][o]
__device__ float g_y2[(size_t)MTOT * CO];         // conv2 pre-BN output [m][o]
__device__ int   g_idx[(size_t)MTOT * 3];
__device__ float g_w[(size_t)MTOT * 3];
__device__ float g_psum[NBLK_STATS * CO];
__device__ float g_psq[NBLK_STATS * CO];
__device__ float g_scale[2][CO];
__device__ float g_shift[2][CO];

// ---------------- transpose feat1 [b][C1][N1] -> g_f1t [b][N1][C1] ----------
__global__ void transpose_f1_kernel(const float* __restrict__ in) {
    __shared__ float t[32][33];
    int b  = blockIdx.z;
    int n0 = blockIdx.x * 32;
    int c0 = blockIdx.y * 32;
    int tx = threadIdx.x, ty = threadIdx.y;     // 32 x 8
    const float* src = in + (size_t)b * C1 * N1;
#pragma unroll
    for (int i = 0; i < 4; i++)
        t[ty + i * 8][tx] = src[(size_t)(c0 + ty + i * 8) * N1 + n0 + tx];
    __syncthreads();
    float* dst = g_f1t + (size_t)b * N1 * C1;
#pragma unroll
    for (int i = 0; i < 4; i++)
        dst[(size_t)(n0 + ty + i * 8) * C1 + c0 + tx] = t[tx][ty + i * 8];
}

// ---------------- transpose feat2 [b][C2][N2] -> xcat cols [C1..C1+C2) -----
__global__ void transpose_f2_kernel(const float* __restrict__ in) {
    __shared__ float t[32][33];
    int b  = blockIdx.z;
    int n0 = blockIdx.x * 32;
    int c0 = blockIdx.y * 32;
    int tx = threadIdx.x, ty = threadIdx.y;
    const float* src = in + (size_t)b * C2 * N2;
#pragma unroll
    for (int i = 0; i < 4; i++)
        t[ty + i * 8][tx] = src[(size_t)(c0 + ty + i * 8) * N2 + n0 + tx];
    __syncthreads();
    float* dst = g_xcat + (size_t)b * N2 * K1;
#pragma unroll
    for (int i = 0; i < 4; i++)
        dst[(size_t)(n0 + ty + i * 8) * K1 + C1 + c0 + tx] = t[tx][ty + i * 8];
}

// ---------------- three_nn: per query point, top-3 nearest in xyz1 ---------
__global__ void knn_kernel(const float* __restrict__ xyz2,
                           const float* __restrict__ xyz1) {
    __shared__ float sx[N1], sy[N1], sz[N1];
    int b = blockIdx.y;
    int n = blockIdx.x * 256 + threadIdx.x;
    const float* p1 = xyz1 + (size_t)b * 3 * N1;
    for (int j = threadIdx.x; j < N1; j += 256) {
        sx[j] = p1[j];
        sy[j] = p1[N1 + j];
        sz[j] = p1[2 * N1 + j];
    }
    __syncthreads();
    const float* p2 = xyz2 + (size_t)b * 3 * N2;
    float px = p2[n], py = p2[N2 + n], pz = p2[2 * N2 + n];

    float d0 = 3.4e38f, d1 = 3.4e38f, d2 = 3.4e38f;
    int   i0 = 0, i1 = 0, i2 = 0;
    for (int j = 0; j < N1; j++) {
        float dx = px - sx[j];
        float dy = py - sy[j];
        float dz = pz - sz[j];
        float d = dx * dx + dy * dy + dz * dz;
        if (d < d2) {                       // rarely taken -> cheap branch
            if (d < d1) {
                d2 = d1; i2 = i1;
                if (d < d0) { d1 = d0; i1 = i0; d0 = d; i0 = j; }
                else        { d1 = d;  i1 = j; }
            } else { d2 = d; i2 = j; }
        }
    }
    d0 = fmaxf(d0, 1e-10f);
    d1 = fmaxf(d1, 1e-10f);
    d2 = fmaxf(d2, 1e-10f);
    float v0 = 1.0f / d0, v1 = 1.0f / d1, v2 = 1.0f / d2;
    float inv = 1.0f / (v0 + v1 + v2);
    size_t p = ((size_t)b * N2 + n) * 3;
    g_idx[p] = i0; g_idx[p + 1] = i1; g_idx[p + 2] = i2;
    g_w[p] = v0 * inv; g_w[p + 1] = v1 * inv; g_w[p + 2] = v2 * inv;
}

// ---------------- weighted gather: xcat cols [0..C1) -----------------------
__global__ void interp_kernel() {
    int warp = (blockIdx.x * blockDim.x + threadIdx.x) >> 5;   // == b*N2+n
    int lane = threadIdx.x & 31;
    int b = warp >> 13;                                        // N2 = 8192
    size_t p3 = (size_t)warp * 3;
    int   i0 = g_idx[p3], i1 = g_idx[p3 + 1], i2 = g_idx[p3 + 2];
    float w0 = g_w[p3],   w1 = g_w[p3 + 1],   w2 = g_w[p3 + 2];
    const float* f  = g_f1t + (size_t)b * N1 * C1;
    const float* r0 = f + (size_t)i0 * C1;
    const float* r1 = f + (size_t)i1 * C1;
    const float* r2 = f + (size_t)i2 * C1;
    float* dst = g_xcat + (size_t)warp * K1;
#pragma unroll
    for (int c = lane; c < C1; c += 32)
        dst[c] = w0 * r0[c] + w1 * r1[c] + w2 * r2[c];
}

// ---------------- SGEMM: C[m][o] = sum_k A[m][k] * W[o][k] -----------------
// STAGE 0: A = g_xcat (K=384) -> g_y1
// STAGE 1: A = relu(bn1(g_y1)) (K=256, transform fused at load) -> g_y2
template <int STAGE>
__global__ void __launch_bounds__(256, 2)
gemm_kernel(const float* __restrict__ W) {
    constexpr int KDIM = (STAGE == 0) ? K1 : CO;
    const float* A = (STAGE == 0) ? g_xcat : g_y1;
    float*       C = (STAGE == 0) ? g_y1 : g_y2;

    __shared__ float As[16][128];
    __shared__ float Bs[16][128];
    __shared__ float sScl[KDIM];
    __shared__ float sShf[KDIM];

    int tid = threadIdx.x;
    if (STAGE == 1) {
        if (tid < KDIM) { sScl[tid] = g_scale[0][tid]; sShf[tid] = g_shift[0][tid]; }
        __syncthreads();
    }

    int bm = blockIdx.x, bn = blockIdx.y;
    int tx = tid & 15, ty = tid >> 4;
    int row0 = ty * 8, col0 = tx * 8;
    int lr = tid >> 2;           // 0..63
    int lc = (tid & 3) * 4;      // 0,4,8,12

    const float* Ab = A + (size_t)(bm * 128) * KDIM;
    const float* Bb = W + (size_t)(bn * 128) * KDIM;

    float acc[8][8];
#pragma unroll
    for (int i = 0; i < 8; i++)
#pragma unroll
        for (int j = 0; j < 8; j++) acc[i][j] = 0.0f;

    for (int kt = 0; kt < KDIM; kt += 16) {
        float4 a0 = *(const float4*)(Ab + (size_t)lr * KDIM + kt + lc);
        float4 a1 = *(const float4*)(Ab + (size_t)(lr + 64) * KDIM + kt + lc);
        float4 b0 = *(const float4*)(Bb + (size_t)lr * KDIM + kt + lc);
        float4 b1 = *(const float4*)(Bb + (size_t)(lr + 64) * KDIM + kt + lc);
        if (STAGE == 1) {
            float s0 = sScl[kt + lc + 0], f0 = sShf[kt + lc + 0];
            float s1 = sScl[kt + lc + 1], f1 = sShf[kt + lc + 1];
            float s2 = sScl[kt + lc + 2], f2 = sShf[kt + lc + 2];
            float s3 = sScl[kt + lc + 3], f3 = sShf[kt + lc + 3];
            a0.x = fmaxf(fmaf(a0.x, s0, f0), 0.0f);
            a0.y = fmaxf(fmaf(a0.y, s1, f1), 0.0f);
            a0.z = fmaxf(fmaf(a0.z, s2, f2), 0.0f);
            a0.w = fmaxf(fmaf(a0.w, s3, f3), 0.0f);
            a1.x = fmaxf(fmaf(a1.x, s0, f0), 0.0f);
            a1.y = fmaxf(fmaf(a1.y, s1, f1), 0.0f);
            a1.z = fmaxf(fmaf(a1.z, s2, f2), 0.0f);
            a1.w = fmaxf(fmaf(a1.w, s3, f3), 0.0f);
        }
        __syncthreads();   // previous tile fully consumed
        As[lc + 0][lr] = a0.x; As[lc + 1][lr] = a0.y;
        As[lc + 2][lr] = a0.z; As[lc + 3][lr] = a0.w;
        As[lc + 0][lr + 64] = a1.x; As[lc + 1][lr + 64] = a1.y;
        As[lc + 2][lr + 64] = a1.z; As[lc + 3][lr + 64] = a1.w;
        Bs[lc + 0][lr] = b0.x; Bs[lc + 1][lr] = b0.y;
        Bs[lc + 2][lr] = b0.z; Bs[lc + 3][lr] = b0.w;
        Bs[lc + 0][lr + 64] = b1.x; Bs[lc + 1][lr + 64] = b1.y;
        Bs[lc + 2][lr + 64] = b1.z; Bs[lc + 3][lr + 64] = b1.w;
        __syncthreads();
#pragma unroll
        for (int k = 0; k < 16; k++) {
            float ar[8], br[8];
            *(float4*)(ar)     = *(const float4*)&As[k][row0];
            *(float4*)(ar + 4) = *(const float4*)&As[k][row0 + 4];
            *(float4*)(br)     = *(const float4*)&Bs[k][col0];
            *(float4*)(br + 4) = *(const float4*)&Bs[k][col0 + 4];
#pragma unroll
            for (int i = 0; i < 8; i++)
#pragma unroll
                for (int j = 0; j < 8; j++)
                    acc[i][j] = fmaf(ar[i], br[j], acc[i][j]);
        }
    }

    float* Cb = C + (size_t)(bm * 128 + row0) * CO + bn * 128 + col0;
#pragma unroll
    for (int i = 0; i < 8; i++) {
        *(float4*)(Cb + (size_t)i * CO)     =
            make_float4(acc[i][0], acc[i][1], acc[i][2], acc[i][3]);
        *(float4*)(Cb + (size_t)i * CO + 4) =
            make_float4(acc[i][4], acc[i][5], acc[i][6], acc[i][7]);
    }
}

// ---------------- per-channel partial sums (deterministic two-pass BN) -----
template <int STAGE>
__global__ void stats_kernel() {
    const float* Y = (STAGE == 0) ? g_y1 : g_y2;
    int blk = blockIdx.x;            // 1024 blocks
    int t   = threadIdx.x;           // 256 threads = 256 channels
    const float* base = Y + (size_t)blk * STATS_ROWS * CO + t;
    float s = 0.0f, q = 0.0f;
#pragma unroll 8
    for (int r = 0; r < STATS_ROWS; r++) {
        float v = base[(size_t)r * CO];
        s += v;
        q += v * v;
    }
    g_psum[blk * CO + t] = s;
    g_psq[blk * CO + t]  = q;
}

__global__ void finalize_kernel(const float* __restrict__ gamma,
                                const float* __restrict__ beta, int stage) {
    __shared__ float ss[256], sq[256];
    int cl  = threadIdx.x & 31;
    int seg = threadIdx.x >> 5;                 // 8 segments
    int c   = blockIdx.x * 32 + cl;             // grid 8 -> 256 channels
    float s = 0.0f, q = 0.0f;
    for (int b2 = seg; b2 < NBLK_STATS; b2 += 8) {
        s += g_psum[b2 * CO + c];
        q += g_psq[b2 * CO + c];
    }
    ss[threadIdx.x] = s; sq[threadIdx.x] = q;
    __syncthreads();
    if (seg == 0) {
        for (int k = 1; k < 8; k++) { s += ss[k * 32 + cl]; q += sq[k * 32 + cl]; }
        float mean = s * (1.0f / MTOT);
        float var  = q * (1.0f / MTOT) - mean * mean;
        float sc   = gamma[c] / sqrtf(var + 1e-3f);
        g_scale[stage][c] = sc;
        g_shift[stage][c] = beta[c] - mean * sc;
    }
}

// ---------------- output: relu(bn2(y2)) + transpose [b,n,o]->[b,o,n] -------
__global__ void output_kernel(float* __restrict__ out) {
    __shared__ float t[32][33];
    int b  = blockIdx.z;
    int n0 = blockIdx.x * 32;
    int o0 = blockIdx.y * 32;
    int tx = threadIdx.x, ty = threadIdx.y;
    const float* Y = g_y2 + (size_t)b * N2 * CO;
#pragma unroll
    for (int i = 0; i < 4; i++) {
        int o = o0 + tx;
        int n = n0 + ty + i * 8;
        float v = Y[(size_t)n * CO + o];
        v = fmaxf(fmaf(v, g_scale[1][o], g_shift[1][o]), 0.0f);
        t[ty + i * 8][tx] = v;
    }
    __syncthreads();
    float* dst = out + (size_t)b * CO * N2;
#pragma unroll
    for (int i = 0; i < 4; i++)
        dst[(size_t)(o0 + ty + i * 8) * N2 + n0 + tx] = t[tx][ty + i * 8];
}

// ---------------- launch ---------------------------------------------------
extern "C" void kernel_launch(void* const* d_in, const int* in_sizes, int n_in,
                              void* d_out, int out_size) {
    const float* xyz2  = (const float*)d_in[0];
    const float* xyz1  = (const float*)d_in[1];
    const float* feat2 = (const float*)d_in[2];
    const float* feat1 = (const float*)d_in[3];
    const float* W1    = (const float*)d_in[4];
    // d_in[5] = b1 (cancels inside BN)
    const float* g1    = (const float*)d_in[6];
    const float* be1   = (const float*)d_in[7];
    const float* W2    = (const float*)d_in[8];
    // d_in[9] = b2 (cancels inside BN)
    const float* g2    = (const float*)d_in[10];
    const float* be2   = (const float*)d_in[11];
    float* out = (float*)d_out;

    dim3 b32(32, 8);
    transpose_f1_kernel<<<dim3(N1 / 32, C1 / 32, BB), b32>>>(feat1);
    transpose_f2_kernel<<<dim3(N2 / 32, C2 / 32, BB), b32>>>(feat2);
    knn_kernel<<<dim3(N2 / 256, BB), 256>>>(xyz2, xyz1);
    interp_kernel<<<MTOT / 8, 256>>>();

    gemm_kernel<0><<<dim3(MTOT / 128, CO / 128), 256>>>(W1);
    stats_kernel<0><<<NBLK_STATS, 256>>>();
    finalize_kernel<<<8, 256>>>(g1, be1, 0);

    gemm_kernel<1><<<dim3(MTOT / 128, CO / 128), 256>>>(W2);
    stats_kernel<1><<<NBLK_STATS, 256>>>();
    finalize_kernel<<<8, 256>>>(g2, be2, 1);

    output_kernel<<<dim3(N2 / 32, CO / 32, BB), b32>>>(out);
}

// round 3
// speedup vs baseline: 1.5085x; 1.5085x over previous
#include <cuda_runtime.h>
#include <math.h>
#include <stdint.h>

#define BB   8
#define N2   8192
#define N1   2048
#define C1   256
#define C2   128
#define K1   384
#define CO   256
#define MTOT 65536
#define GCTAS 512                 // GEMM m-blocks (M-tile = 128)
#define STG_BYTES 30720           // A 128*80 + B 256*80
#define DSM_BYTES (3 * STG_BYTES)

// ---------------- scratch (static device globals) --------------------------
__device__ float g_f1t[(size_t)BB * N1 * C1];
__device__ float g_xcat[(size_t)MTOT * K1];
__device__ float g_y1[(size_t)MTOT * CO];
__device__ float g_x2[(size_t)MTOT * CO];
__device__ float g_y2[(size_t)MTOT * CO];
__device__ float g_w1r[CO * K1];
__device__ float g_w2r[CO * CO];
__device__ int   g_idx[(size_t)MTOT * 3];
__device__ float g_w[(size_t)MTOT * 3];
__device__ float g_psum[GCTAS * CO];
__device__ float g_psq[GCTAS * CO];
__device__ float g_scale[2][CO];
__device__ float g_shift[2][CO];

// ---------------- helpers ---------------------------------------------------
__device__ __forceinline__ uint32_t smem_u32(const void* p) {
    uint32_t a;
    asm("{ .reg .u64 t; cvta.to.shared.u64 t, %1; cvt.u32.u64 %0, t; }"
        : "=r"(a) : "l"(p));
    return a;
}
__device__ __forceinline__ float rtf32(float x) {
    uint32_t u;
    asm("cvt.rn.tf32.f32 %0, %1;" : "=r"(u) : "f"(x));
    return __uint_as_float(u);
}
__device__ __forceinline__ void ldsm4(uint32_t* r, uint32_t addr) {
    asm volatile("ldmatrix.sync.aligned.m8n8.x4.shared.b16 {%0,%1,%2,%3}, [%4];"
                 : "=r"(r[0]), "=r"(r[1]), "=r"(r[2]), "=r"(r[3]) : "r"(addr));
}
__device__ __forceinline__ void mma_tf32(float* c, const uint32_t* a,
                                         uint32_t b0, uint32_t b1) {
    asm volatile(
        "mma.sync.aligned.m16n8k8.row.col.f32.tf32.tf32.f32 "
        "{%0,%1,%2,%3}, {%4,%5,%6,%7}, {%8,%9}, {%0,%1,%2,%3};"
        : "+f"(c[0]), "+f"(c[1]), "+f"(c[2]), "+f"(c[3])
        : "r"(a[0]), "r"(a[1]), "r"(a[2]), "r"(a[3]), "r"(b0), "r"(b1));
}
__device__ __forceinline__ void cpasync16(uint32_t s, const void* g) {
    asm volatile("cp.async.cg.shared.global [%0], [%1], 16;" :: "r"(s), "l"(g));
}

// ---------------- transpose feat1 [b][C1][N1] -> g_f1t [b][N1][C1] ----------
__global__ void transpose_f1_kernel(const float* __restrict__ in) {
    __shared__ float t[32][33];
    int b = blockIdx.z, n0 = blockIdx.x * 32, c0 = blockIdx.y * 32;
    int tx = threadIdx.x, ty = threadIdx.y;
    const float* src = in + (size_t)b * C1 * N1;
#pragma unroll
    for (int i = 0; i < 4; i++)
        t[ty + i * 8][tx] = src[(size_t)(c0 + ty + i * 8) * N1 + n0 + tx];
    __syncthreads();
    float* dst = g_f1t + (size_t)b * N1 * C1;
#pragma unroll
    for (int i = 0; i < 4; i++)
        dst[(size_t)(n0 + ty + i * 8) * C1 + c0 + tx] = t[tx][ty + i * 8];
}

// ---------------- transpose feat2 -> xcat cols [C1..K1), tf32-rounded ------
__global__ void transpose_f2_kernel(const float* __restrict__ in) {
    __shared__ float t[32][33];
    int b = blockIdx.z, n0 = blockIdx.x * 32, c0 = blockIdx.y * 32;
    int tx = threadIdx.x, ty = threadIdx.y;
    const float* src = in + (size_t)b * C2 * N2;
#pragma unroll
    for (int i = 0; i < 4; i++)
        t[ty + i * 8][tx] = src[(size_t)(c0 + ty + i * 8) * N2 + n0 + tx];
    __syncthreads();
    float* dst = g_xcat + (size_t)b * N2 * K1;
#pragma unroll
    for (int i = 0; i < 4; i++)
        dst[(size_t)(n0 + ty + i * 8) * K1 + C1 + c0 + tx] = rtf32(t[tx][ty + i * 8]);
}

// ---------------- three_nn (float4-packed smem, broadcast reads) -----------
__global__ void knn_kernel(const float* __restrict__ xyz2,
                           const float* __restrict__ xyz1) {
    __shared__ float4 s4[N1];
    int b = blockIdx.y;
    int n = blockIdx.x * 256 + threadIdx.x;
    const float* p1 = xyz1 + (size_t)b * 3 * N1;
    for (int j = threadIdx.x; j < N1; j += 256)
        s4[j] = make_float4(p1[j], p1[N1 + j], p1[2 * N1 + j], 0.0f);
    __syncthreads();
    const float* p2 = xyz2 + (size_t)b * 3 * N2;
    float px = p2[n], py = p2[N2 + n], pz = p2[2 * N2 + n];
    float d0 = 3.4e38f, d1 = 3.4e38f, d2 = 3.4e38f;
    int   i0 = 0, i1 = 0, i2 = 0;
#pragma unroll 2
    for (int j = 0; j < N1; j++) {
        float4 v = s4[j];
        float dx = px - v.x, dy = py - v.y, dz = pz - v.z;
        float d = dx * dx + dy * dy + dz * dz;
        if (d < d2) {
            if (d < d1) {
                d2 = d1; i2 = i1;
                if (d < d0) { d1 = d0; i1 = i0; d0 = d; i0 = j; }
                else        { d1 = d;  i1 = j; }
            } else { d2 = d; i2 = j; }
        }
    }
    d0 = fmaxf(d0, 1e-10f); d1 = fmaxf(d1, 1e-10f); d2 = fmaxf(d2, 1e-10f);
    float v0 = 1.0f / d0, v1 = 1.0f / d1, v2 = 1.0f / d2;
    float inv = 1.0f / (v0 + v1 + v2);
    size_t p = ((size_t)b * N2 + n) * 3;
    g_idx[p] = i0; g_idx[p + 1] = i1; g_idx[p + 2] = i2;
    g_w[p] = v0 * inv; g_w[p + 1] = v1 * inv; g_w[p + 2] = v2 * inv;
}

// ---------------- weighted gather -> xcat cols [0..C1), tf32-rounded -------
__global__ void interp_kernel() {
    int warp = (blockIdx.x * blockDim.x + threadIdx.x) >> 5;
    int lane = threadIdx.x & 31;
    int b = warp >> 13;
    size_t p3 = (size_t)warp * 3;
    int   i0 = g_idx[p3], i1 = g_idx[p3 + 1], i2 = g_idx[p3 + 2];
    float w0 = g_w[p3],   w1 = g_w[p3 + 1],   w2 = g_w[p3 + 2];
    const float* f  = g_f1t + (size_t)b * N1 * C1;
    const float* r0 = f + (size_t)i0 * C1;
    const float* r1 = f + (size_t)i1 * C1;
    const float* r2 = f + (size_t)i2 * C1;
    float* dst = g_xcat + (size_t)warp * K1;
#pragma unroll
    for (int c = lane; c < C1; c += 32)
        dst[c] = rtf32(w0 * r0[c] + w1 * r1[c] + w2 * r2[c]);
}

// ---------------- round weights to tf32 ------------------------------------
__global__ void round_w_kernel(const float* __restrict__ W1,
                               const float* __restrict__ W2) {
    int i = blockIdx.x * 256 + threadIdx.x;
    if (i < CO * K1) g_w1r[i] = rtf32(W1[i]);
    if (i < CO * CO) g_w2r[i] = rtf32(W2[i]);
}

// ---------------- tf32 mma.sync GEMM: C[m][o] = sum_k A[m][k]*W[o][k] ------
// CTA tile 128m x 256n, 8 warps (4m x 2n), warp tile 32x128, k-chunk 16.
// 3-stage cp.async pipeline; smem rows padded to 80B (conflict-free ldmatrix).
// Fused per-CTA BN partial stats in epilogue.
template <int STAGE>
__global__ void __launch_bounds__(256, 1) gemm_mma() {
    constexpr int KD = (STAGE == 0) ? K1 : CO;
    constexpr int S  = KD / 16;
    const float* A  = (STAGE == 0) ? g_xcat : g_x2;
    const float* W  = (STAGE == 0) ? g_w1r  : g_w2r;
    float* Cout     = (STAGE == 0) ? g_y1   : g_y2;

    extern __shared__ char dsm[];
    uint32_t sbase = smem_u32(dsm);
    int tid = threadIdx.x, lane = tid & 31, wid = tid >> 5;
    int wm = wid & 3, wn = wid >> 2;
    int m0 = blockIdx.x * 128;
    const float* Ab = A + (size_t)m0 * KD;

    float c[2][16][4];
#pragma unroll
    for (int i = 0; i < 2; i++)
#pragma unroll
        for (int t = 0; t < 16; t++)
#pragma unroll
            for (int r = 0; r < 4; r++) c[i][t][r] = 0.0f;

    // prologue: stages 0, 1
#pragma unroll
    for (int ps = 0; ps < 2; ps++) {
        uint32_t st = sbase + ps * STG_BYTES;
        for (int i = tid; i < 1536; i += 256) {
            if (i < 512) {
                int row = i >> 2, cc = i & 3;
                cpasync16(st + row * 80 + cc * 16,
                          Ab + (size_t)row * KD + ps * 16 + cc * 4);
            } else {
                int j = i - 512, row = j >> 2, cc = j & 3;
                cpasync16(st + 10240 + row * 80 + cc * 16,
                          W + (size_t)row * KD + ps * 16 + cc * 4);
            }
        }
        asm volatile("cp.async.commit_group;" ::: "memory");
    }

    // per-lane fragment base offsets (bytes)
    uint32_t aoff = (uint32_t)((wm * 32 + (lane & 15)) * 80 + ((lane >> 4) << 4));
    uint32_t boff = (uint32_t)(10240 +
        (wn * 128 + (lane & 7) + ((lane >> 4) << 3)) * 80 + (((lane >> 3) & 1) << 4));

    for (int s = 0; s < S; s++) {
        asm volatile("cp.async.wait_group 1;" ::: "memory");
        __syncthreads();
        // issue stage s+2
        {
            int ns = s + 2;
            if (ns < S) {
                uint32_t st = sbase + (ns % 3) * STG_BYTES;
                for (int i = tid; i < 1536; i += 256) {
                    if (i < 512) {
                        int row = i >> 2, cc = i & 3;
                        cpasync16(st + row * 80 + cc * 16,
                                  Ab + (size_t)row * KD + ns * 16 + cc * 4);
                    } else {
                        int j = i - 512, row = j >> 2, cc = j & 3;
                        cpasync16(st + 10240 + row * 80 + cc * 16,
                                  W + (size_t)row * KD + ns * 16 + cc * 4);
                    }
                }
            }
            asm volatile("cp.async.commit_group;" ::: "memory");
        }
        uint32_t st = sbase + (s % 3) * STG_BYTES;
#pragma unroll
        for (int kk = 0; kk < 2; kk++) {
            uint32_t a0[4], a1[4];
            ldsm4(a0, st + aoff + kk * 32);
            ldsm4(a1, st + aoff + 16 * 80 + kk * 32);
#pragma unroll
            for (int tp = 0; tp < 8; tp++) {
                uint32_t bfr[4];
                ldsm4(bfr, st + boff + tp * 16 * 80 + kk * 32);
                mma_tf32(c[0][2 * tp],     a0, bfr[0], bfr[1]);
                mma_tf32(c[0][2 * tp + 1], a0, bfr[2], bfr[3]);
                mma_tf32(c[1][2 * tp],     a1, bfr[0], bfr[1]);
                mma_tf32(c[1][2 * tp + 1], a1, bfr[2], bfr[3]);
            }
        }
    }
    __syncthreads();

    // ---- epilogue: store C + fused BN partial stats ----
    float* sredS = (float*)dsm;          // [4][256]
    float* sredQ = sredS + 1024;         // [4][256]
#pragma unroll
    for (int mi = 0; mi < 2; mi++) {
        int row0 = m0 + wm * 32 + mi * 16 + (lane >> 2);
#pragma unroll
        for (int t = 0; t < 16; t++) {
            int col = wn * 128 + t * 8 + (lane & 3) * 2;
            *(float2*)(Cout + (size_t)row0 * CO + col) =
                make_float2(c[mi][t][0], c[mi][t][1]);
            *(float2*)(Cout + (size_t)(row0 + 8) * CO + col) =
                make_float2(c[mi][t][2], c[mi][t][3]);
        }
    }
#pragma unroll
    for (int t = 0; t < 16; t++) {
        float s0 = c[0][t][0] + c[0][t][2] + c[1][t][0] + c[1][t][2];
        float s1 = c[0][t][1] + c[0][t][3] + c[1][t][1] + c[1][t][3];
        float q0 = c[0][t][0] * c[0][t][0] + c[0][t][2] * c[0][t][2] +
                   c[1][t][0] * c[1][t][0] + c[1][t][2] * c[1][t][2];
        float q1 = c[0][t][1] * c[0][t][1] + c[0][t][3] * c[0][t][3] +
                   c[1][t][1] * c[1][t][1] + c[1][t][3] * c[1][t][3];
#pragma unroll
        for (int o = 4; o <= 16; o <<= 1) {
            s0 += __shfl_xor_sync(0xffffffffu, s0, o);
            s1 += __shfl_xor_sync(0xffffffffu, s1, o);
            q0 += __shfl_xor_sync(0xffffffffu, q0, o);
            q1 += __shfl_xor_sync(0xffffffffu, q1, o);
        }
        if (lane < 4) {
            int col = wn * 128 + t * 8 + lane * 2;
            sredS[wm * 256 + col] = s0; sredS[wm * 256 + col + 1] = s1;
            sredQ[wm * 256 + col] = q0; sredQ[wm * 256 + col + 1] = q1;
        }
    }
    __syncthreads();
    {
        float s = 0.0f, q = 0.0f;
#pragma unroll
        for (int w = 0; w < 4; w++) { s += sredS[w * 256 + tid]; q += sredQ[w * 256 + tid]; }
        g_psum[blockIdx.x * CO + tid] = s;
        g_psq[blockIdx.x * CO + tid]  = q;
    }
}

// ---------------- finalize BN stats -> scale/shift -------------------------
__global__ void finalize_kernel(const float* __restrict__ gamma,
                                const float* __restrict__ beta, int stage) {
    int c = threadIdx.x;
    float s = 0.0f, q = 0.0f;
    for (int b = 0; b < GCTAS; b++) { s += g_psum[b * CO + c]; q += g_psq[b * CO + c]; }
    float mean = s * (1.0f / MTOT);
    float var  = q * (1.0f / MTOT) - mean * mean;
    float sc   = gamma[c] / sqrtf(var + 1e-3f);
    g_scale[stage][c] = sc;
    g_shift[stage][c] = beta[c] - mean * sc;
}

// ---------------- apply BN1+ReLU, tf32-round -> g_x2 -----------------------
__global__ void apply_bn1() {
    size_t i = (size_t)blockIdx.x * 256 + threadIdx.x;
    float4 v = ((const float4*)g_y1)[i];
    int c = (int)((i * 4) & (CO - 1));
    float4 o;
    o.x = rtf32(fmaxf(fmaf(v.x, g_scale[0][c],     g_shift[0][c]),     0.0f));
    o.y = rtf32(fmaxf(fmaf(v.y, g_scale[0][c + 1], g_shift[0][c + 1]), 0.0f));
    o.z = rtf32(fmaxf(fmaf(v.z, g_scale[0][c + 2], g_shift[0][c + 2]), 0.0f));
    o.w = rtf32(fmaxf(fmaf(v.w, g_scale[0][c + 3], g_shift[0][c + 3]), 0.0f));
    ((float4*)g_x2)[i] = o;
}

// ---------------- output: relu(bn2(y2)) + transpose [b,n,o]->[b,o,n] -------
__global__ void output_kernel(float* __restrict__ out) {
    __shared__ float t[32][33];
    int b = blockIdx.z, n0 = blockIdx.x * 32, o0 = blockIdx.y * 32;
    int tx = threadIdx.x, ty = threadIdx.y;
    const float* Y = g_y2 + (size_t)b * N2 * CO;
#pragma unroll
    for (int i = 0; i < 4; i++) {
        int o = o0 + tx;
        int n = n0 + ty + i * 8;
        float v = Y[(size_t)n * CO + o];
        t[ty + i * 8][tx] = fmaxf(fmaf(v, g_scale[1][o], g_shift[1][o]), 0.0f);
    }
    __syncthreads();
    float* dst = out + (size_t)b * CO * N2;
#pragma unroll
    for (int i = 0; i < 4; i++)
        dst[(size_t)(o0 + ty + i * 8) * N2 + n0 + tx] = t[tx][ty + i * 8];
}

// ---------------- launch ---------------------------------------------------
extern "C" void kernel_launch(void* const* d_in, const int* in_sizes, int n_in,
                              void* d_out, int out_size) {
    const float* xyz2  = (const float*)d_in[0];
    const float* xyz1  = (const float*)d_in[1];
    const float* feat2 = (const float*)d_in[2];
    const float* feat1 = (const float*)d_in[3];
    const float* W1    = (const float*)d_in[4];
    const float* g1    = (const float*)d_in[6];
    const float* be1   = (const float*)d_in[7];
    const float* W2    = (const float*)d_in[8];
    const float* g2    = (const float*)d_in[10];
    const float* be2   = (const float*)d_in[11];
    float* out = (float*)d_out;

    cudaFuncSetAttribute(gemm_mma<0>, cudaFuncAttributeMaxDynamicSharedMemorySize, DSM_BYTES);
    cudaFuncSetAttribute(gemm_mma<1>, cudaFuncAttributeMaxDynamicSharedMemorySize, DSM_BYTES);

    dim3 b32(32, 8);
    transpose_f1_kernel<<<dim3(N1 / 32, C1 / 32, BB), b32>>>(feat1);
    transpose_f2_kernel<<<dim3(N2 / 32, C2 / 32, BB), b32>>>(feat2);
    knn_kernel<<<dim3(N2 / 256, BB), 256>>>(xyz2, xyz1);
    interp_kernel<<<MTOT / 8, 256>>>();
    round_w_kernel<<<(CO * K1 + 255) / 256, 256>>>(W1, W2);

    gemm_mma<0><<<GCTAS, 256, DSM_BYTES>>>();
    finalize_kernel<<<1, 256>>>(g1, be1, 0);
    apply_bn1<<<(MTOT * CO / 4) / 256, 256>>>();

    gemm_mma<1><<<GCTAS, 256, DSM_BYTES>>>();
    finalize_kernel<<<1, 256>>>(g2, be2, 1);

    output_kernel<<<dim3(N2 / 32, CO / 32, BB), b32>>>(out);
}

// round 4
// speedup vs baseline: 1.6047x; 1.0638x over previous
#include <cuda_runtime.h>
#include <math.h>
#include <stdint.h>

#define BB   8
#define N2   8192
#define N1   2048
#define C1   256
#define C2   128
#define K1   384
#define CO   256
#define MTOT 65536
#define GCTAS 512                 // GEMM m-blocks (M-tile = 128)
#define STG_BYTES 30720           // A 128*80 + B 256*80
#define DSM_BYTES (3 * STG_BYTES)

// ---------------- scratch (static device globals) --------------------------
__device__ float g_f1t[(size_t)BB * N1 * C1];
__device__ float g_xcat[(size_t)MTOT * K1];
__device__ float g_y1[(size_t)MTOT * CO];
__device__ float g_y2[(size_t)MTOT * CO];
__device__ float g_w1r[CO * K1];
__device__ float g_w2r[CO * CO];
__device__ int   g_idx[(size_t)MTOT * 3];
__device__ float g_w[(size_t)MTOT * 3];
__device__ float g_psum[GCTAS * CO];
__device__ float g_psq[GCTAS * CO];
__device__ float g_scale[2][CO];
__device__ float g_shift[2][CO];

// ---------------- helpers ---------------------------------------------------
__device__ __forceinline__ uint32_t smem_u32(const void* p) {
    uint32_t a;
    asm("{ .reg .u64 t; cvta.to.shared.u64 t, %1; cvt.u32.u64 %0, t; }"
        : "=r"(a) : "l"(p));
    return a;
}
__device__ __forceinline__ float rtf32(float x) {
    uint32_t u;
    asm("cvt.rn.tf32.f32 %0, %1;" : "=r"(u) : "f"(x));
    return __uint_as_float(u);
}
__device__ __forceinline__ void ldsm4(uint32_t* r, uint32_t addr) {
    asm volatile("ldmatrix.sync.aligned.m8n8.x4.shared.b16 {%0,%1,%2,%3}, [%4];"
                 : "=r"(r[0]), "=r"(r[1]), "=r"(r[2]), "=r"(r[3]) : "r"(addr));
}
__device__ __forceinline__ void mma_tf32(float* c, const uint32_t* a,
                                         uint32_t b0, uint32_t b1) {
    asm volatile(
        "mma.sync.aligned.m16n8k8.row.col.f32.tf32.tf32.f32 "
        "{%0,%1,%2,%3}, {%4,%5,%6,%7}, {%8,%9}, {%0,%1,%2,%3};"
        : "+f"(c[0]), "+f"(c[1]), "+f"(c[2]), "+f"(c[3])
        : "r"(a[0]), "r"(a[1]), "r"(a[2]), "r"(a[3]), "r"(b0), "r"(b1));
}
__device__ __forceinline__ void cpasync16(uint32_t s, const void* g) {
    asm volatile("cp.async.cg.shared.global [%0], [%1], 16;" :: "r"(s), "l"(g));
}

// ---------------- transpose feat1 [b][C1][N1] -> g_f1t [b][N1][C1] ----------
__global__ void transpose_f1_kernel(const float* __restrict__ in) {
    __shared__ float t[32][33];
    int b = blockIdx.z, n0 = blockIdx.x * 32, c0 = blockIdx.y * 32;
    int tx = threadIdx.x, ty = threadIdx.y;
    const float* src = in + (size_t)b * C1 * N1;
#pragma unroll
    for (int i = 0; i < 4; i++)
        t[ty + i * 8][tx] = src[(size_t)(c0 + ty + i * 8) * N1 + n0 + tx];
    __syncthreads();
    float* dst = g_f1t + (size_t)b * N1 * C1;
#pragma unroll
    for (int i = 0; i < 4; i++)
        dst[(size_t)(n0 + ty + i * 8) * C1 + c0 + tx] = t[tx][ty + i * 8];
}

// ---------------- transpose feat2 -> xcat cols [C1..K1), tf32-rounded ------
__global__ void transpose_f2_kernel(const float* __restrict__ in) {
    __shared__ float t[32][33];
    int b = blockIdx.z, n0 = blockIdx.x * 32, c0 = blockIdx.y * 32;
    int tx = threadIdx.x, ty = threadIdx.y;
    const float* src = in + (size_t)b * C2 * N2;
#pragma unroll
    for (int i = 0; i < 4; i++)
        t[ty + i * 8][tx] = src[(size_t)(c0 + ty + i * 8) * N2 + n0 + tx];
    __syncthreads();
    float* dst = g_xcat + (size_t)b * N2 * K1;
#pragma unroll
    for (int i = 0; i < 4; i++)
        dst[(size_t)(n0 + ty + i * 8) * K1 + C1 + c0 + tx] = rtf32(t[tx][ty + i * 8]);
}

// ---------------- three_nn --------------------------------------------------
__global__ void knn_kernel(const float* __restrict__ xyz2,
                           const float* __restrict__ xyz1) {
    __shared__ float4 s4[N1];
    int b = blockIdx.y;
    int n = blockIdx.x * 256 + threadIdx.x;
    const float* p1 = xyz1 + (size_t)b * 3 * N1;
    for (int j = threadIdx.x; j < N1; j += 256)
        s4[j] = make_float4(p1[j], p1[N1 + j], p1[2 * N1 + j], 0.0f);
    __syncthreads();
    const float* p2 = xyz2 + (size_t)b * 3 * N2;
    float px = p2[n], py = p2[N2 + n], pz = p2[2 * N2 + n];
    float d0 = 3.4e38f, d1 = 3.4e38f, d2 = 3.4e38f;
    int   i0 = 0, i1 = 0, i2 = 0;
#pragma unroll 2
    for (int j = 0; j < N1; j++) {
        float4 v = s4[j];
        float dx = px - v.x, dy = py - v.y, dz = pz - v.z;
        float d = dx * dx + dy * dy + dz * dz;
        if (d < d2) {
            if (d < d1) {
                d2 = d1; i2 = i1;
                if (d < d0) { d1 = d0; i1 = i0; d0 = d; i0 = j; }
                else        { d1 = d;  i1 = j; }
            } else { d2 = d; i2 = j; }
        }
    }
    d0 = fmaxf(d0, 1e-10f); d1 = fmaxf(d1, 1e-10f); d2 = fmaxf(d2, 1e-10f);
    float v0 = 1.0f / d0, v1 = 1.0f / d1, v2 = 1.0f / d2;
    float inv = 1.0f / (v0 + v1 + v2);
    size_t p = ((size_t)b * N2 + n) * 3;
    g_idx[p] = i0; g_idx[p + 1] = i1; g_idx[p + 2] = i2;
    g_w[p] = v0 * inv; g_w[p + 1] = v1 * inv; g_w[p + 2] = v2 * inv;
}

// ---------------- weighted gather -> xcat cols [0..C1), float4, tf32 -------
__global__ void interp_kernel() {
    int warp = (blockIdx.x * blockDim.x + threadIdx.x) >> 5;
    int lane = threadIdx.x & 31;
    int b = warp >> 13;
    size_t p3 = (size_t)warp * 3;
    int   i0 = g_idx[p3], i1 = g_idx[p3 + 1], i2 = g_idx[p3 + 2];
    float w0 = g_w[p3],   w1 = g_w[p3 + 1],   w2 = g_w[p3 + 2];
    const float* f = g_f1t + (size_t)b * N1 * C1;
    const float4* r0 = (const float4*)(f + (size_t)i0 * C1);
    const float4* r1 = (const float4*)(f + (size_t)i1 * C1);
    const float4* r2 = (const float4*)(f + (size_t)i2 * C1);
    float4* dst = (float4*)(g_xcat + (size_t)warp * K1);
#pragma unroll
    for (int c = lane; c < C1 / 4; c += 32) {
        float4 a = r0[c], e = r1[c], d = r2[c], o;
        o.x = rtf32(fmaf(w0, a.x, fmaf(w1, e.x, w2 * d.x)));
        o.y = rtf32(fmaf(w0, a.y, fmaf(w1, e.y, w2 * d.y)));
        o.z = rtf32(fmaf(w0, a.z, fmaf(w1, e.z, w2 * d.z)));
        o.w = rtf32(fmaf(w0, a.w, fmaf(w1, e.w, w2 * d.w)));
        dst[c] = o;
    }
}

// ---------------- round weights to tf32 ------------------------------------
__global__ void round_w_kernel(const float* __restrict__ W1,
                               const float* __restrict__ W2) {
    int i = blockIdx.x * 256 + threadIdx.x;
    if (i < CO * K1) g_w1r[i] = rtf32(W1[i]);
    if (i < CO * CO) g_w2r[i] = rtf32(W2[i]);
}

// ---------------- tf32 mma.sync GEMM: C[m][o] = sum_k A[m][k]*W[o][k] ------
// CTA tile 128m x 256n, 16 warps (4m x 4n), warp tile 32x64, k-chunk 16.
// 3-stage pipeline. STAGE 0: A = g_xcat via cp.async (K=384).
// STAGE 1: A = relu(bn1(g_y1)) via LDG+transform+STS (K=256); B cp.async.
// Fused per-CTA BN partial stats in epilogue.
template <int STAGE>
__global__ void __launch_bounds__(512, 1) gemm_mma() {
    constexpr int KD = (STAGE == 0) ? K1 : CO;
    constexpr int S  = KD / 16;
    const float* W  = (STAGE == 0) ? g_w1r : g_w2r;
    float* Cout     = (STAGE == 0) ? g_y1  : g_y2;

    extern __shared__ char dsm[];
    __shared__ float s_scl[CO], s_shf[CO];
    uint32_t sbase = smem_u32(dsm);
    int tid = threadIdx.x, lane = tid & 31, wid = tid >> 5;
    int wm = wid & 3, wn = wid >> 2;
    int m0 = blockIdx.x * 128;
    int arow = tid >> 2, aseg = tid & 3;     // one float4 of A per thread/stage

    if (STAGE == 1) {
        if (tid < CO) { s_scl[tid] = g_scale[0][tid]; s_shf[tid] = g_shift[0][tid]; }
        __syncthreads();
    }

    const float* Ag = ((STAGE == 0) ? g_xcat : g_y1) + (size_t)m0 * KD;
    float4 va;                                // prefetched A (STAGE 1)

    auto ldA = [&](int s) -> float4 {
        float4 v = *(const float4*)(Ag + (size_t)arow * KD + s * 16 + aseg * 4);
        int k = s * 16 + aseg * 4;
        v.x = rtf32(fmaxf(fmaf(v.x, s_scl[k],     s_shf[k]),     0.0f));
        v.y = rtf32(fmaxf(fmaf(v.y, s_scl[k + 1], s_shf[k + 1]), 0.0f));
        v.z = rtf32(fmaxf(fmaf(v.z, s_scl[k + 2], s_shf[k + 2]), 0.0f));
        v.w = rtf32(fmaxf(fmaf(v.w, s_scl[k + 3], s_shf[k + 3]), 0.0f));
        return v;
    };
    auto issueB = [&](int s) {
        uint32_t st = sbase + (s % 3) * STG_BYTES + 10240;
        for (int i = tid; i < 1024; i += 512) {
            int row = i >> 2, seg = i & 3;
            cpasync16(st + row * 80 + seg * 16, W + (size_t)row * KD + s * 16 + seg * 4);
        }
    };
    auto issueA_async = [&](int s) {
        uint32_t st = sbase + (s % 3) * STG_BYTES;
        cpasync16(st + arow * 80 + aseg * 16, Ag + (size_t)arow * KD + s * 16 + aseg * 4);
    };

    float c[2][8][4];
#pragma unroll
    for (int i = 0; i < 2; i++)
#pragma unroll
        for (int t = 0; t < 8; t++)
#pragma unroll
            for (int r = 0; r < 4; r++) c[i][t][r] = 0.0f;

    // ---- prologue: stages 0, 1 ----
    if (STAGE == 0) {
        issueA_async(0); issueB(0);
        asm volatile("cp.async.commit_group;" ::: "memory");
        issueA_async(1); issueB(1);
        asm volatile("cp.async.commit_group;" ::: "memory");
    } else {
        float4 v0 = ldA(0);
        *(float4*)(dsm + 0 * STG_BYTES + arow * 80 + aseg * 16) = v0;
        issueB(0);
        asm volatile("cp.async.commit_group;" ::: "memory");
        va = ldA(1);
        issueB(1);
        asm volatile("cp.async.commit_group;" ::: "memory");
    }

    uint32_t aoff = (uint32_t)((wm * 32 + (lane & 15)) * 80 + ((lane >> 4) << 4));
    uint32_t boff = (uint32_t)(10240 +
        (wn * 64 + (lane & 7) + ((lane >> 4) << 3)) * 80 + (((lane >> 3) & 1) << 4));

    for (int s = 0; s < S; s++) {
        asm volatile("cp.async.wait_group 1;" ::: "memory");
        __syncthreads();
        if (STAGE == 1) {
            if (s + 1 < S)
                *(float4*)(dsm + ((s + 1) % 3) * STG_BYTES + arow * 80 + aseg * 16) = va;
            if (s + 2 < S) va = ldA(s + 2);
            if (s + 2 < S) issueB(s + 2);
        } else {
            if (s + 2 < S) { issueA_async(s + 2); issueB(s + 2); }
        }
        asm volatile("cp.async.commit_group;" ::: "memory");

        uint32_t st = sbase + (s % 3) * STG_BYTES;
#pragma unroll
        for (int kk = 0; kk < 2; kk++) {
            uint32_t a0[4], a1[4];
            ldsm4(a0, st + aoff + kk * 32);
            ldsm4(a1, st + aoff + 16 * 80 + kk * 32);
#pragma unroll
            for (int tp = 0; tp < 4; tp++) {
                uint32_t bfr[4];
                ldsm4(bfr, st + boff + tp * 16 * 80 + kk * 32);
                mma_tf32(c[0][2 * tp],     a0, bfr[0], bfr[1]);
                mma_tf32(c[0][2 * tp + 1], a0, bfr[2], bfr[3]);
                mma_tf32(c[1][2 * tp],     a1, bfr[0], bfr[1]);
                mma_tf32(c[1][2 * tp + 1], a1, bfr[2], bfr[3]);
            }
        }
    }
    __syncthreads();

    // ---- epilogue: store C + fused BN partial stats ----
    float* sredS = (float*)dsm;              // [16][64]
    float* sredQ = sredS + 1024;             // [16][64]
#pragma unroll
    for (int mi = 0; mi < 2; mi++) {
        int row0 = m0 + wm * 32 + mi * 16 + (lane >> 2);
#pragma unroll
        for (int t = 0; t < 8; t++) {
            int col = wn * 64 + t * 8 + (lane & 3) * 2;
            *(float2*)(Cout + (size_t)row0 * CO + col) =
                make_float2(c[mi][t][0], c[mi][t][1]);
            *(float2*)(Cout + (size_t)(row0 + 8) * CO + col) =
                make_float2(c[mi][t][2], c[mi][t][3]);
        }
    }
#pragma unroll
    for (int t = 0; t < 8; t++) {
        float s0 = c[0][t][0] + c[0][t][2] + c[1][t][0] + c[1][t][2];
        float s1 = c[0][t][1] + c[0][t][3] + c[1][t][1] + c[1][t][3];
        float q0 = c[0][t][0] * c[0][t][0] + c[0][t][2] * c[0][t][2] +
                   c[1][t][0] * c[1][t][0] + c[1][t][2] * c[1][t][2];
        float q1 = c[0][t][1] * c[0][t][1] + c[0][t][3] * c[0][t][3] +
                   c[1][t][1] * c[1][t][1] + c[1][t][3] * c[1][t][3];
#pragma unroll
        for (int o = 4; o <= 16; o <<= 1) {
            s0 += __shfl_xor_sync(0xffffffffu, s0, o);
            s1 += __shfl_xor_sync(0xffffffffu, s1, o);
            q0 += __shfl_xor_sync(0xffffffffu, q0, o);
            q1 += __shfl_xor_sync(0xffffffffu, q1, o);
        }
        if (lane < 4) {
            int col = t * 8 + lane * 2;
            sredS[wid * 64 + col] = s0; sredS[wid * 64 + col + 1] = s1;
            sredQ[wid * 64 + col] = q0; sredQ[wid * 64 + col + 1] = q1;
        }
    }
    __syncthreads();
    if (tid < CO) {
        int wg = tid >> 6, cl = tid & 63;
        float s = 0.0f, q = 0.0f;
#pragma unroll
        for (int w = 0; w < 4; w++) {
            s += sredS[(wg * 4 + w) * 64 + cl];
            q += sredQ[(wg * 4 + w) * 64 + cl];
        }
        g_psum[blockIdx.x * CO + tid] = s;
        g_psq[blockIdx.x * CO + tid]  = q;
    }
}

// ---------------- finalize BN stats -> scale/shift -------------------------
__global__ void finalize_kernel(const float* __restrict__ gamma,
                                const float* __restrict__ beta, int stage) {
    int c = threadIdx.x;
    float s = 0.0f, q = 0.0f;
    for (int b = 0; b < GCTAS; b++) { s += g_psum[b * CO + c]; q += g_psq[b * CO + c]; }
    float mean = s * (1.0f / MTOT);
    float var  = q * (1.0f / MTOT) - mean * mean;
    float sc   = gamma[c] / sqrtf(var + 1e-3f);
    g_scale[stage][c] = sc;
    g_shift[stage][c] = beta[c] - mean * sc;
}

// ---------------- output: relu(bn2(y2)) + transpose [b,n,o]->[b,o,n] -------
__global__ void output_kernel(float* __restrict__ out) {
    __shared__ float t[32][33];
    int b = blockIdx.z, n0 = blockIdx.x * 32, o0 = blockIdx.y * 32;
    int tx = threadIdx.x, ty = threadIdx.y;
    const float* Y = g_y2 + (size_t)b * N2 * CO;
#pragma unroll
    for (int i = 0; i < 4; i++) {
        int o = o0 + tx;
        int n = n0 + ty + i * 8;
        float v = Y[(size_t)n * CO + o];
        t[ty + i * 8][tx] = fmaxf(fmaf(v, g_scale[1][o], g_shift[1][o]), 0.0f);
    }
    __syncthreads();
    float* dst = out + (size_t)b * CO * N2;
#pragma unroll
    for (int i = 0; i < 4; i++)
        dst[(size_t)(o0 + ty + i * 8) * N2 + n0 + tx] = t[tx][ty + i * 8];
}

// ---------------- launch ---------------------------------------------------
extern "C" void kernel_launch(void* const* d_in, const int* in_sizes, int n_in,
                              void* d_out, int out_size) {
    const float* xyz2  = (const float*)d_in[0];
    const float* xyz1  = (const float*)d_in[1];
    const float* feat2 = (const float*)d_in[2];
    const float* feat1 = (const float*)d_in[3];
    const float* W1    = (const float*)d_in[4];
    const float* g1    = (const float*)d_in[6];
    const float* be1   = (const float*)d_in[7];
    const float* W2    = (const float*)d_in[8];
    const float* g2    = (const float*)d_in[10];
    const float* be2   = (const float*)d_in[11];
    float* out = (float*)d_out;

    cudaFuncSetAttribute(gemm_mma<0>, cudaFuncAttributeMaxDynamicSharedMemorySize, DSM_BYTES);
    cudaFuncSetAttribute(gemm_mma<1>, cudaFuncAttributeMaxDynamicSharedMemorySize, DSM_BYTES);

    dim3 b32(32, 8);
    transpose_f1_kernel<<<dim3(N1 / 32, C1 / 32, BB), b32>>>(feat1);
    transpose_f2_kernel<<<dim3(N2 / 32, C2 / 32, BB), b32>>>(feat2);
    knn_kernel<<<dim3(N2 / 256, BB), 256>>>(xyz2, xyz1);
    interp_kernel<<<MTOT / 8, 256>>>();
    round_w_kernel<<<(CO * K1 + 255) / 256, 256>>>(W1, W2);

    gemm_mma<0><<<GCTAS, 512, DSM_BYTES>>>();
    finalize_kernel<<<1, 256>>>(g1, be1, 0);

    gemm_mma<1><<<GCTAS, 512, DSM_BYTES>>>();
    finalize_kernel<<<1, 256>>>(g2, be2, 1);

    output_kernel<<<dim3(N2 / 32, CO / 32, BB), b32>>>(out);
}